// round 11
// baseline (speedup 1.0000x reference)
#include <cuda_runtime.h>
#include <cuda_bf16.h>
#include <math.h>
#include <stdint.h>

#define BATCH 32768
#define DIM   256
#define CBK   1024
#define LVL   8
#define BM    128
#define GRID  (BATCH / BM)           // 256
#define MU    1e-4f                  // rescue margin (3-pass hard error bound ~1e-6)

// smem byte offsets
#define SO_A    0                    // A tile [128 rows][512 k=hi|lo] bf16, 1024B rows = 131072
#define SO_B    131072               // B slabs 2 x {Bh,Bl}[64 codes][128 k] = 65536
#define SO_EE   196608               // 1024 floats
#define SO_SV   200704               // 4 n-warps x 128 rows x 2
#define SO_SI   204800               // same, ints
#define SO_IDX  208896               // 128 ints (+pad)
#define SO_RED  209408               // 512 floats
#define SO_CNT  211456               // rescue counter (+pad)
#define SO_RQ   211472               // 128 entries x 6 ints
#define SMEM_BYTES 214544

// ---------------- device scratch ----------------
__device__ float g_resid[BATCH * DIM];
__device__ float g_qsum [BATCH * DIM];
__device__ float g_xx   [BATCH];
__device__ float g_ee   [LVL * CBK];
__device__ int   g_idx  [BATCH * LVL];
__device__ float g_commit_part[LVL * GRID];
__device__ int   g_counts[CBK];
__device__ __nv_bfloat16 g_ah[BATCH * DIM];        // residual hi
__device__ __nv_bfloat16 g_al[BATCH * DIM];        // residual lo
__device__ __nv_bfloat16 g_bh[LVL * CBK * DIM];    // codebook hi
__device__ __nv_bfloat16 g_bl[LVL * CBK * DIM];    // codebook lo

// ---------------- helpers ----------------
__device__ __forceinline__ uint32_t smem_u32(const void* p) {
    uint32_t a;
    asm("{ .reg .u64 t; cvta.to.shared.u64 t, %1; cvt.u32.u64 %0, t; }" : "=r"(a) : "l"(p));
    return a;
}
#define CP16(dst, src) asm volatile("cp.async.cg.shared.global [%0], [%1], 16;" :: "r"(dst), "l"(src))
#define CPCOMMIT()     asm volatile("cp.async.commit_group;" ::: "memory")
#define CPWAIT1()      asm volatile("cp.async.wait_group 1;" ::: "memory")
#define CPWAIT0()      asm volatile("cp.async.wait_group 0;" ::: "memory")

__device__ __forceinline__ void ldsm_x4(uint32_t* r, uint32_t addr) {
    asm volatile("ldmatrix.sync.aligned.m8n8.x4.shared.b16 {%0,%1,%2,%3}, [%4];"
        : "=r"(r[0]), "=r"(r[1]), "=r"(r[2]), "=r"(r[3]) : "r"(addr));
}
__device__ __forceinline__ void mma_bf16(float* d, const uint32_t* a, const uint32_t* b) {
    asm volatile("mma.sync.aligned.m16n8k16.row.col.f32.bf16.bf16.f32 "
        "{%0,%1,%2,%3}, {%4,%5,%6,%7}, {%8,%9}, {%0,%1,%2,%3};"
        : "+f"(d[0]), "+f"(d[1]), "+f"(d[2]), "+f"(d[3])
        : "r"(a[0]), "r"(a[1]), "r"(a[2]), "r"(a[3]), "r"(b[0]), "r"(b[1]));
}

// ---------------- prep kernels ----------------
__global__ void k_prepB(const float* __restrict__ emb)
{
    int i = blockIdx.x * blockDim.x + threadIdx.x;
    if (i >= LVL * CBK * DIM) return;
    float x = emb[i];
    __nv_bfloat16 h = __float2bfloat16(x);
    g_bh[i] = h;
    g_bl[i] = __float2bfloat16(x - __bfloat162float(h));
}

__global__ void k_eeinit(const float* __restrict__ emb)
{
    int gt = blockIdx.x * blockDim.x + threadIdx.x;
    if (gt < CBK) g_counts[gt] = 0;
    int gw   = blockIdx.x * (blockDim.x >> 5) + (threadIdx.x >> 5);
    int lane = threadIdx.x & 31;
    if (gw >= LVL * CBK) return;
    const float* r = emb + (size_t)gw * DIM;
    float s = 0.f;
#pragma unroll
    for (int j = 0; j < 8; j++) { float v = r[lane + 32 * j]; s = fmaf(v, v, s); }
#pragma unroll
    for (int o = 16; o; o >>= 1) s += __shfl_xor_sync(0xffffffffu, s, o);
    if (!lane) g_ee[gw] = s;
}

__global__ void k_prepA(const float* __restrict__ z)
{
    int gw   = blockIdx.x * (blockDim.x >> 5) + (threadIdx.x >> 5);
    int lane = threadIdx.x & 31;
    if (gw >= BATCH) return;
    const float* r = z + (size_t)gw * DIM;
    float s = 0.f;
#pragma unroll
    for (int j = 0; j < 8; j++) {
        float v = r[lane + 32 * j];
        __nv_bfloat16 h = __float2bfloat16(v);
        g_ah[(size_t)gw * DIM + lane + 32 * j] = h;
        g_al[(size_t)gw * DIM + lane + 32 * j] = __float2bfloat16(v - __bfloat162float(h));
        s = fmaf(v, v, s);
    }
#pragma unroll
    for (int o = 16; o; o >>= 1) s += __shfl_xor_sync(0xffffffffu, s, o);
    if (!lane) g_xx[gw] = s;
}

// ---------------- main per-level kernel: 3-pass HMMA + top-3 + exact rescue --------
// 256 CTAs x 512 threads (16 warps = 4m x 4n, warp tile 32x16). A hi|lo resident;
// B slabs {Bh,Bl}[64 codes][128 k] double-buffered; 32 steps. hh+hl+lh accumulate
// into ONE fp32 accumulator (hard error bound ~1e-6 << MU).
__global__ void __launch_bounds__(512, 1)
k_level(const float* __restrict__ z,
        const float* __restrict__ cb,
        int level,
        float* __restrict__ o_idx_f)
{
    extern __shared__ char smem[];
    uint32_t sb = smem_u32(smem);
    float* ee_s  = (float*)(smem + SO_EE);
    float* sv    = (float*)(smem + SO_SV);
    int*   si    = (int*)(smem + SO_SI);
    int*   s_idx = (int*)(smem + SO_IDX);
    float* s_red = (float*)(smem + SO_RED);
    int*   s_cnt = (int*)(smem + SO_CNT);
    int*   rq    = (int*)(smem + SO_RQ);

    const int tid = threadIdx.x, wid = tid >> 5, lane = tid & 31;
    const int wm = wid >> 2, wn = wid & 3;
    const int row0 = blockIdx.x * BM;
    const int first = (level == 0);
    const float* A_src = first ? z : g_resid;
    const __nv_bfloat16* pbh = g_bh + (size_t)level * CBK * DIM;
    const __nv_bfloat16* pbl = g_bl + (size_t)level * CBK * DIM;

    if (tid == 0) *s_cnt = 0;

    // ---- A tile: [128 rows][512 = hi(0-255)|lo(256-511)] bf16, 1024B rows, swizzled ----
    {
#pragma unroll
        for (int i = 0; i < 16; i++) {
            int ch = i * 512 + tid;                    // 8192 chunks of 16B
            int m = ch >> 6, kc = ch & 63;
            const __nv_bfloat16* src = (kc < 32)
                ? (g_ah + (size_t)(row0 + m) * DIM + kc * 8)
                : (g_al + (size_t)(row0 + m) * DIM + (kc - 32) * 8);
            uint32_t dst = sb + SO_A + m * 1024 + ((kc * 16) ^ ((m & 7) << 4));
            CP16(dst, src);
        }
        CPCOMMIT();
    }
    for (int i = tid; i < CBK; i += 512) ee_s[i] = g_ee[level * CBK + i];

    const int q2   = (lane & 3) * 2;
    const int rthr = lane >> 2;
    const int arow = ((lane >> 3) & 1) * 8 + (lane & 7);
    const int kofA = (lane >> 4) * 8;
    const int brow = ((lane >> 4) & 1) * 8 + (lane & 7);
    const int kofB = ((lane >> 3) & 1) * 8;

    uint32_t aOff[2]; int aKey[2];
#pragma unroll
    for (int im = 0; im < 2; im++) {
        int m = wm * 32 + im * 16 + arow;
        aOff[im] = sb + SO_A + m * 1024;
        aKey[im] = (m & 7) << 4;
    }
    uint32_t bOff; int bKey;
    {
        int nr = wn * 16 + brow;
        bOff = nr * 256;
        bKey = (nr & 7) << 4;
    }
    float xr[4];
#pragma unroll
    for (int i = 0; i < 4; i++)
        xr[i] = g_xx[row0 + wm * 32 + (i >> 1) * 16 + (i & 1) * 8 + rthr];

    float acc[2][2][4];                  // [im][jj(n8)][d0..d3] = 16 regs
#pragma unroll
    for (int a = 0; a < 2; a++)
#pragma unroll
        for (int b = 0; b < 2; b++)
#pragma unroll
            for (int c = 0; c < 4; c++) acc[a][b][c] = 0.f;
    float v1[4], v2[4]; int i1[4], i2[4];
#pragma unroll
    for (int i = 0; i < 4; i++) { v1[i] = 3.4e38f; v2[i] = 3.4e38f; i1[i] = 1 << 29; i2[i] = 1 << 29; }

    // B slab s: codes [nt*64,+64), k-half [half*128,+128); Bh at +0, Bl at +16384
    auto loadB = [&](int s) {
        int nt = s >> 1, half = s & 1;
        uint32_t dB = sb + SO_B + (s & 1) * 32768;
#pragma unroll
        for (int i = 0; i < 2; i++) {
            int ch = i * 512 + tid;                    // 1024 chunks (16KB)
            int r = ch >> 4, kc = ch & 15;
            uint32_t sw = r * 256 + ((kc * 16) ^ ((r & 7) << 4));
            CP16(dB + sw,         pbh + (size_t)(nt * 64 + r) * DIM + half * 128 + kc * 8);
        }
#pragma unroll
        for (int i = 0; i < 2; i++) {
            int ch = i * 512 + tid;
            int r = ch >> 4, kc = ch & 15;
            uint32_t sw = r * 256 + ((kc * 16) ^ ((r & 7) << 4));
            CP16(dB + 16384 + sw, pbl + (size_t)(nt * 64 + r) * DIM + half * 128 + kc * 8);
        }
        CPCOMMIT();
    };

    loadB(0);

#define UPD(rp, dval, cidx) do { \
        if ((dval) < v1[rp]) { v2[rp] = v1[rp]; i2[rp] = i1[rp]; v1[rp] = (dval); i1[rp] = (cidx); } \
        else if ((dval) < v2[rp]) { v2[rp] = (dval); i2[rp] = (cidx); } } while (0)

    // ---- mainloop: 16 N-chunks (64 codes) x 2 k-halves = 32 steps ----
    for (int s = 0; s < 32; s++) {
        if (s + 1 < 32) { loadB(s + 1); CPWAIT1(); } else { CPWAIT0(); }
        __syncthreads();
        int nt = s >> 1, half = s & 1;
        uint32_t bB = sb + SO_B + (s & 1) * 32768;
#pragma unroll
        for (int kc = 0; kc < 8; kc++) {
            uint32_t bh[4], bl[4];
            uint32_t kb = (((kc * 16 + kofB) << 1)) ^ bKey;
            ldsm_x4(bh, bB + bOff + kb);
            ldsm_x4(bl, bB + 16384 + bOff + kb);
            uint32_t afh[2][4], afl[2][4];
            int kh = half * 128 + kc * 16;             // Ah col range
            int kl = 256 + kh;                         // Al col range
#pragma unroll
            for (int im = 0; im < 2; im++) {
                ldsm_x4(afh[im], aOff[im] + ((((kh + kofA) << 1)) ^ aKey[im]));
                ldsm_x4(afl[im], aOff[im] + ((((kl + kofA) << 1)) ^ aKey[im]));
            }
#pragma unroll
            for (int im = 0; im < 2; im++) {
                mma_bf16(acc[im][0], afh[im], &bh[0]);     // hh
                mma_bf16(acc[im][1], afh[im], &bh[2]);
                mma_bf16(acc[im][0], afh[im], &bl[0]);     // hl
                mma_bf16(acc[im][1], afh[im], &bl[2]);
                mma_bf16(acc[im][0], afl[im], &bh[0]);     // lh
                mma_bf16(acc[im][1], afl[im], &bh[2]);
            }
        }
        if (half) {                                     // N-chunk done: score + top-2
#pragma unroll
            for (int im = 0; im < 2; im++)
#pragma unroll
                for (int jj = 0; jj < 2; jj++) {
                    int col = nt * 64 + wn * 16 + jj * 8 + q2;
                    float e0 = ee_s[col], e1 = ee_s[col + 1];
                    float d;
                    d = (xr[im * 2] + e0) - 2.0f * acc[im][jj][0];
                    UPD(im * 2, d, col);
                    d = (xr[im * 2] + e1) - 2.0f * acc[im][jj][1];
                    UPD(im * 2, d, col + 1);
                    d = (xr[im * 2 + 1] + e0) - 2.0f * acc[im][jj][2];
                    UPD(im * 2 + 1, d, col);
                    d = (xr[im * 2 + 1] + e1) - 2.0f * acc[im][jj][3];
                    UPD(im * 2 + 1, d, col + 1);
                    acc[im][jj][0] = 0.f; acc[im][jj][1] = 0.f;
                    acc[im][jj][2] = 0.f; acc[im][jj][3] = 0.f;
                }
        }
        __syncthreads();
    }

    // ---- top-2 merge across the 4 lanes sharing rthr, store per n-warp top-2 ----
#pragma unroll
    for (int i = 0; i < 4; i++) {
        float a1 = v1[i], a2 = v2[i]; int b1 = i1[i], b2 = i2[i];
#pragma unroll
        for (int o = 1; o <= 2; o <<= 1) {
            float u1 = __shfl_xor_sync(0xffffffffu, a1, o);
            float u2 = __shfl_xor_sync(0xffffffffu, a2, o);
            int   j1 = __shfl_xor_sync(0xffffffffu, b1, o);
            int   j2 = __shfl_xor_sync(0xffffffffu, b2, o);
            if (u1 < a1 || (u1 == a1 && j1 < b1)) {
                if (a1 < u2 || (a1 == u2 && b1 < j2)) { a2 = a1; b2 = b1; }
                else                                  { a2 = u2; b2 = j2; }
                a1 = u1; b1 = j1;
            } else {
                if (u1 < a2 || (u1 == a2 && j1 < b2)) { a2 = u1; b2 = j1; }
            }
        }
        if ((lane & 3) == 0) {
            int row = wm * 32 + (i >> 1) * 16 + (i & 1) * 8 + rthr;
            sv[wn * 256 + row * 2]     = a1; si[wn * 256 + row * 2]     = b1;
            sv[wn * 256 + row * 2 + 1] = a2; si[wn * 256 + row * 2 + 1] = b2;
        }
    }
    __syncthreads();

    // ---- per-row global top-3 scan + rescue decision (thread tid = row) ----
    if (tid < 128) {
        float w0 = 3.4e38f, w1 = 3.4e38f, w2 = 3.4e38f;
        int   x0 = 1 << 30, x1 = 1 << 30, x2 = 1 << 30;
#pragma unroll
        for (int w = 0; w < 4; w++)
#pragma unroll
            for (int s2 = 0; s2 < 2; s2++) {
                float v = sv[w * 256 + tid * 2 + s2];
                int  ix = si[w * 256 + tid * 2 + s2];
                if (v < w0 || (v == w0 && ix < x0)) {
                    w2 = w1; x2 = x1; w1 = w0; x1 = x0; w0 = v; x0 = ix;
                } else if (v < w1 || (v == w1 && ix < x1)) {
                    w2 = w1; x2 = x1; w1 = v; x1 = ix;
                } else if (v < w2 || (v == w2 && ix < x2)) {
                    w2 = v; x2 = ix;
                }
            }
        if (w1 > w0 + MU) {                 // provably unambiguous
            s_idx[tid] = x0;
            int gr = row0 + tid;
            g_idx[(size_t)gr * LVL + level] = x0;
            if (o_idx_f) o_idx_f[(size_t)gr * LVL + level] = (float)x0;
        } else {
            int pos = atomicAdd(s_cnt, 1);
            rq[pos * 6 + 0] = tid;
            rq[pos * 6 + 1] = (w2 <= w0 + MU) ? 3 : 2;
            rq[pos * 6 + 2] = x0; rq[pos * 6 + 3] = x1; rq[pos * 6 + 4] = x2;
        }
    }
    __syncthreads();

    // ---- rescue: exact fp32 sequential-k dd for queued candidates ----
    {
        int cnt = *s_cnt;
        for (int e = wid; e < cnt; e += 16) {
            int row = rq[e * 6], n = rq[e * 6 + 1];
            float dd = 3.4e38f; int ci = 1 << 30;
            if (lane < n) {
                ci = rq[e * 6 + 2 + lane];
                const float* a  = A_src + (size_t)(row0 + row) * DIM;
                const float* ep = cb + (size_t)ci * DIM;
                float dot = 0.f;
#pragma unroll 4
                for (int k = 0; k < 256; k++) dot = fmaf(a[k], ep[k], dot);
                dd = (g_xx[row0 + row] + ee_s[ci]) - 2.0f * dot;
            }
#pragma unroll
            for (int o = 1; o <= 2; o <<= 1) {
                float ov = __shfl_xor_sync(0xffffffffu, dd, o);
                int   oi = __shfl_xor_sync(0xffffffffu, ci, o);
                if (ov < dd || (ov == dd && oi < ci)) { dd = ov; ci = oi; }
            }
            if (lane == 0) {
                s_idx[row] = ci;
                int gr = row0 + row;
                g_idx[(size_t)gr * LVL + level] = ci;
                if (o_idx_f) o_idx_f[(size_t)gr * LVL + level] = (float)ci;
            }
        }
    }
    __syncthreads();

    // ---- fused epilogue: residual, qsum, bf16 hi/lo for next level, xx, commit ----
    {
        int r4 = tid >> 2, dq = (tid & 3) << 6;     // 4 threads/row, 64 dims each
        int gi = s_idx[r4];
        const float* ev = cb + (size_t)gi * DIM + dq;
        size_t gofs = (size_t)(row0 + r4) * DIM + dq;
        const float* av = A_src + gofs;
        float* ro = g_resid + gofs;
        float* qo = g_qsum + gofs;
        __nv_bfloat162* ho  = (__nv_bfloat162*)(g_ah + gofs);
        __nv_bfloat162* lo2 = (__nv_bfloat162*)(g_al + gofs);
        float ss = 0.f;
#pragma unroll 4
        for (int j = 0; j < 16; j++) {
            float4 a = *(const float4*)(av + j * 4);
            float4 e = *(const float4*)(ev + j * 4);
            float4 rn = make_float4(a.x - e.x, a.y - e.y, a.z - e.z, a.w - e.w);
            *(float4*)(ro + j * 4) = rn;
            float4 q;
            if (first) q = e;
            else {
                float4 qp = *(const float4*)(qo + j * 4);
                q = make_float4(qp.x + e.x, qp.y + e.y, qp.z + e.z, qp.w + e.w);
            }
            *(float4*)(qo + j * 4) = q;
            __nv_bfloat162 h0 = __floats2bfloat162_rn(rn.x, rn.y);
            __nv_bfloat162 h1 = __floats2bfloat162_rn(rn.z, rn.w);
            __nv_bfloat162 l0 = __floats2bfloat162_rn(rn.x - __bfloat162float(h0.x),
                                                      rn.y - __bfloat162float(h0.y));
            __nv_bfloat162 l1 = __floats2bfloat162_rn(rn.z - __bfloat162float(h1.x),
                                                      rn.w - __bfloat162float(h1.y));
            ho[j * 2] = h0; ho[j * 2 + 1] = h1;
            lo2[j * 2] = l0; lo2[j * 2 + 1] = l1;
            ss = fmaf(rn.x, rn.x, ss); ss = fmaf(rn.y, rn.y, ss);
            ss = fmaf(rn.z, rn.z, ss); ss = fmaf(rn.w, rn.w, ss);
        }
        s_red[tid] = ss;
        __syncthreads();
        if (!(tid & 3))
            g_xx[row0 + r4] = (s_red[tid] + s_red[tid + 1]) + (s_red[tid + 2] + s_red[tid + 3]);
        __syncthreads();
#pragma unroll
        for (int o = 256; o; o >>= 1) {
            if (tid < o) s_red[tid] += s_red[tid + o];
            __syncthreads();
        }
        if (!tid) g_commit_part[level * GRID + blockIdx.x] = s_red[0];
    }
#undef UPD
}

// ---------------- histogram ----------------
__global__ void k_count()
{
    __shared__ int h[CBK];
    for (int i = threadIdx.x; i < CBK; i += blockDim.x) h[i] = 0;
    __syncthreads();
    int stride = gridDim.x * blockDim.x;
    for (int i = blockIdx.x * blockDim.x + threadIdx.x; i < BATCH * LVL; i += stride)
        atomicAdd(&h[g_idx[i]], 1);
    __syncthreads();
    for (int i = threadIdx.x; i < CBK; i += blockDim.x) {
        int v = h[i];
        if (v) atomicAdd(&g_counts[i], v);
    }
}

// ---------------- z_q ----------------
__global__ void k_zq(const float* __restrict__ z, float* __restrict__ out)
{
    int n = BATCH * DIM / 4;
    for (int i = blockIdx.x * blockDim.x + threadIdx.x; i < n; i += gridDim.x * blockDim.x) {
        float4 zv = ((const float4*)z)[i];
        float4 qv = ((const float4*)g_qsum)[i];
        float4 t = make_float4(qv.x - zv.x, qv.y - zv.y, qv.z - zv.z, qv.w - zv.w);
        ((float4*)out)[i] = make_float4(zv.x + t.x, zv.y + t.y, zv.z + t.z, zv.w + t.w);
    }
}

// ---------------- scalars ----------------
__global__ void k_final(float* __restrict__ o_sc)
{
    __shared__ float se[1024];
    __shared__ float sc[LVL];
    int t = threadIdx.x;
    float p = (float)g_counts[t] / 262144.0f;
    se[t] = (p > 0.f) ? p * logf(p + 1e-10f) : 0.f;
    __syncthreads();
#pragma unroll
    for (int o = 512; o; o >>= 1) {
        if (t < o) se[t] += se[t + o];
        __syncthreads();
    }
    int w = t >> 5, lane = t & 31;
    if (w < LVL) {
        float s = 0.f;
        for (int b = lane; b < GRID; b += 32) s += g_commit_part[w * GRID + b];
#pragma unroll
        for (int o = 16; o; o >>= 1) s += __shfl_xor_sync(0xffffffffu, s, o);
        if (!lane) sc[w] = s;
    }
    __syncthreads();
    if (!t && o_sc) {
        float ent = -se[0];
        float total = 0.f;
        for (int l = 0; l < LVL; l++) total += sc[l] / 8388608.0f;
        o_sc[0] = 0.25f * total;
        o_sc[1] = total;
        o_sc[2] = expf(ent);
    }
}

// ---------------- launch ----------------
extern "C" void kernel_launch(void* const* d_in, const int* in_sizes, int n_in,
                              void* d_out, int out_size)
{
    const float* z   = (const float*)d_in[0];
    const float* emb = (const float*)d_in[1];
    if (n_in >= 2 && in_sizes[0] == LVL * CBK * DIM && in_sizes[1] == BATCH * DIM) {
        emb = (const float*)d_in[0];
        z   = (const float*)d_in[1];
    }

    cudaFuncSetAttribute(k_level, cudaFuncAttributeMaxDynamicSharedMemorySize, SMEM_BYTES);

    float* out = (float*)d_out;
    const long NZQ = (long)BATCH * DIM;   // 8388608
    const long NI  = (long)BATCH * LVL;   // 262144
    float* o_zq  = ((long)out_size >= NZQ)          ? out             : nullptr;
    float* o_idx = ((long)out_size >= NZQ + NI)     ? out + NZQ       : nullptr;
    float* o_sc  = ((long)out_size >= NZQ + NI + 3) ? out + NZQ + NI  : nullptr;

    k_prepB<<<(LVL * CBK * DIM) / 256, 256>>>(emb);
    k_eeinit<<<(LVL * CBK) / 8, 256>>>(emb);
    k_prepA<<<BATCH / 8, 256>>>(z);
    for (int l = 0; l < LVL; l++)
        k_level<<<GRID, 512, SMEM_BYTES>>>(z, emb + (size_t)l * CBK * DIM, l, o_idx);
    k_count<<<64, 256>>>();
    if (o_zq) k_zq<<<2048, 256>>>(z, o_zq);
    k_final<<<1, 1024>>>(o_sc);
}